// round 2
// baseline (speedup 1.0000x reference)
#include <cuda_runtime.h>
#include <cuda_fp16.h>
#include <cstdint>
#include <cstddef>

// Problem shape (fixed by setup_inputs)
#define B_ 64
#define S_ 512
#define E_ 512
#define H_ 1024

// ---------------- device scratch (static; no cudaMalloc allowed) -------------
__device__ __half g_Wih0T[(size_t)H_ * E_];   // [n][e]  (transposed, fp16)
__device__ __half g_Whh0T[(size_t)H_ * H_];   // [n][k]
__device__ __half g_Wih1T[(size_t)H_ * H_];   // [n][k]
__device__ __half g_Whh1T[(size_t)H_ * H_];   // [n][k]
__device__ float  g_bias0[H_];
__device__ float  g_bias1[H_];
__device__ __half g_X0[(size_t)S_ * B_ * H_]; // [t][b][n] = (emb[src] @ W_ih0), fp16
__device__ __half g_h0[2][B_ * H_];           // ping-pong fp16 hidden, layer 0
__device__ __half g_h1[2][B_ * H_];           // ping-pong fp16 hidden, layer 1
__device__ float  g_h0f[B_ * H_];             // latest h0 in fp32 (for final hidden)
__device__ int    g_is64;                     // src dtype flag

// ---------------- mma.sync helper (m16n8k16 fp16 -> fp32) --------------------
__device__ __forceinline__ void mma16816(float* c, const uint32_t* a, const uint32_t* b) {
    asm volatile(
        "mma.sync.aligned.m16n8k16.row.col.f32.f16.f16.f32 "
        "{%0,%1,%2,%3}, {%4,%5,%6,%7}, {%8,%9}, {%0,%1,%2,%3};\n"
        : "+f"(c[0]), "+f"(c[1]), "+f"(c[2]), "+f"(c[3])
        : "r"(a[0]), "r"(a[1]), "r"(a[2]), "r"(a[3]), "r"(b[0]), "r"(b[1]));
}

// ---------------- src dtype detection (int64 vs int32) -----------------------
__global__ void k_detect(const int* src32) {
    __shared__ int bad;
    if (threadIdx.x == 0) bad = 0;
    __syncthreads();
    // If src is int64 (LE), odd 32-bit words are all-zero high words.
    if (src32[2 * threadIdx.x + 1] != 0) atomicExch(&bad, 1);
    __syncthreads();
    if (threadIdx.x == 0) g_is64 = bad ? 0 : 1;
}

// ---------------- weight transpose + fp16 convert ----------------------------
// dst[n*K + k] = w[k*H_ + n]   (all weight matrices have N = H_ output cols)
__global__ void k_convT(const float* __restrict__ w, int which) {
    __half* dst; int K;
    switch (which) {
        case 0:  dst = g_Wih0T; K = E_; break;
        case 1:  dst = g_Whh0T; K = H_; break;
        case 2:  dst = g_Wih1T; K = H_; break;
        default: dst = g_Whh1T; K = H_; break;
    }
    size_t total = (size_t)K * H_;
    for (size_t i = (size_t)blockIdx.x * blockDim.x + threadIdx.x; i < total;
         i += (size_t)gridDim.x * blockDim.x) {
        size_t n = i / (size_t)K;
        size_t k = i - n * (size_t)K;
        dst[i] = __float2half(w[k * H_ + n]);
    }
}

__global__ void k_bias(const float* bih0, const float* bhh0,
                       const float* bih1, const float* bhh1) {
    int i = blockIdx.x * blockDim.x + threadIdx.x;
    if (i < H_) {
        g_bias0[i] = bih0[i] + bhh0[i];
        g_bias1[i] = bih1[i] + bhh1[i];
    }
}

// ---------------- phase 1: X0 = emb[src] @ W_ih0 (gather-GEMM) ----------------
// CTA tile 64(M) x 64(N), K = 512, 256 threads = 8 warps (2M x 4N), warp 32x16.
// m = t*64 + b; a 64-aligned M-tile shares a single t = blockIdx.y.
__global__ void __launch_bounds__(256) k_phase1(const void* srcv, const float* __restrict__ emb) {
    __shared__ __half sA[64][72];
    __shared__ __half sB[64][72];
    __shared__ int    sSrc[64];

    const int* s32 = (const int*)srcv;
    int tid = threadIdx.x;
    int nt = blockIdx.x;          // 0..15
    int mt = blockIdx.y;          // 0..511 == t
    int n0 = nt * 64;

    if (tid < 64) {
        int idx = tid * S_ + mt;  // src[b][t], b = tid
        sSrc[tid] = g_is64 ? s32[2 * idx] : s32[idx];
    }
    __syncthreads();

    int warp = tid >> 5, lane = tid & 31;
    int g = lane >> 2, tg = lane & 3;
    int wm = warp >> 2, wn = warp & 3;

    float acc[2][2][4];
#pragma unroll
    for (int i = 0; i < 2; i++)
#pragma unroll
        for (int j = 0; j < 2; j++)
#pragma unroll
            for (int q = 0; q < 4; q++) acc[i][j][q] = 0.f;

    for (int kc = 0; kc < E_; kc += 64) {
        __syncthreads();
        // A: gather 64 embedding rows x 64 fp32, convert to fp16
#pragma unroll
        for (int it = 0; it < 4; it++) {
            int idx = tid + it * 256;
            int r = idx >> 4, c4 = idx & 15;
            float4 v = *(const float4*)(emb + (size_t)sSrc[r] * E_ + kc + c4 * 4);
            *(__half2*)&sA[r][c4 * 4]     = __floats2half2_rn(v.x, v.y);
            *(__half2*)&sA[r][c4 * 4 + 2] = __floats2half2_rn(v.z, v.w);
        }
        // B: 64 n-rows x 64 k fp16 from transposed weight
#pragma unroll
        for (int it = 0; it < 2; it++) {
            int idx = tid + it * 256;
            int r = idx >> 3, c8 = idx & 7;
            *(uint4*)&sB[r][c8 * 8] =
                *(const uint4*)(g_Wih0T + (size_t)(n0 + r) * E_ + kc + c8 * 8);
        }
        __syncthreads();
#pragma unroll
        for (int kk = 0; kk < 64; kk += 16) {
            uint32_t af[2][4], bf[2][2];
#pragma unroll
            for (int ms = 0; ms < 2; ms++) {
                int rb = wm * 32 + ms * 16;
                af[ms][0] = *(const uint32_t*)&sA[rb + g][kk + tg * 2];
                af[ms][1] = *(const uint32_t*)&sA[rb + g + 8][kk + tg * 2];
                af[ms][2] = *(const uint32_t*)&sA[rb + g][kk + tg * 2 + 8];
                af[ms][3] = *(const uint32_t*)&sA[rb + g + 8][kk + tg * 2 + 8];
            }
#pragma unroll
            for (int ns = 0; ns < 2; ns++) {
                int nc = wn * 16 + ns * 8 + g;
                bf[ns][0] = *(const uint32_t*)&sB[nc][kk + tg * 2];
                bf[ns][1] = *(const uint32_t*)&sB[nc][kk + tg * 2 + 8];
            }
#pragma unroll
            for (int ms = 0; ms < 2; ms++)
#pragma unroll
                for (int ns = 0; ns < 2; ns++) mma16816(acc[ms][ns], af[ms], bf[ns]);
        }
    }
    // epilogue: store X0 (fp16)
#pragma unroll
    for (int ms = 0; ms < 2; ms++)
#pragma unroll
        for (int ns = 0; ns < 2; ns++) {
            int n = n0 + wn * 16 + ns * 8 + tg * 2;
#pragma unroll
            for (int hh = 0; hh < 2; hh++) {
                int row = wm * 32 + ms * 16 + g + hh * 8;
                size_t m = (size_t)mt * 64 + row;
                *(__half2*)&g_X0[m * H_ + n] =
                    __floats2half2_rn(acc[ms][ns][hh * 2], acc[ms][ns][hh * 2 + 1]);
            }
        }
}

// ---------------- init: h0_0 = tanh(X0[0] + bias0), h1_{-1} = 0 ---------------
__global__ void k_init() {
    int i = blockIdx.x * blockDim.x + threadIdx.x;
    if (i < B_ * H_) {
        int n = i & (H_ - 1);
        float h = tanhf(__half2float(g_X0[i]) + g_bias0[n]);
        g_h0[0][i] = __float2half(h);
        g_h0f[i] = h;
        g_h1[0][i] = __float2half(0.f);
    }
}

// ---------------- step kernel: one launch per timestep ------------------------
// blocks 0..31  : layer0 -> h0_{t+1} = tanh(X0[t+1] + h0_t @ W_hh0 + bias0)
// blocks 32..63 : layer1 -> h1_t     = tanh(h0_t @ W_ih1 + h1_{t-1} @ W_hh1 + bias1)
// CTA tile 64(M=batch) x 32(N), 128 threads = 4 warps (2M x 2N), warp 32x16.
__global__ void __launch_bounds__(128) k_step(int t, float* __restrict__ out) {
    __shared__ __half sA[64][72];
    __shared__ __half sB[32][72];

    int tid = threadIdx.x;
    int warp = tid >> 5, lane = tid & 31;
    int g = lane >> 2, tg = lane & 3;
    int wm = warp >> 1, wn = warp & 1;
    int layer = (int)(blockIdx.x >> 5);
    int nt = (int)(blockIdx.x & 31);
    int n0 = nt * 32;
    int p = t & 1;

    if (layer == 0 && t + 1 >= S_) return;  // uniform per block

    float acc[2][2][4];
#pragma unroll
    for (int i = 0; i < 2; i++)
#pragma unroll
        for (int j = 0; j < 2; j++)
#pragma unroll
            for (int q = 0; q < 4; q++) acc[i][j][q] = 0.f;

    int nPh = (layer == 0) ? 1 : 2;
    for (int ph = 0; ph < nPh; ph++) {
        const __half* A = (ph == 0) ? g_h0[p] : g_h1[p];
        const __half* Bm = (layer == 0) ? g_Whh0T : ((ph == 0) ? g_Wih1T : g_Whh1T);
        for (int kc = 0; kc < H_; kc += 64) {
            __syncthreads();
            // A: 64 x 64 fp16 (full batch of h)
#pragma unroll
            for (int it = 0; it < 4; it++) {
                int idx = tid + it * 128;
                int r = idx >> 3, c8 = idx & 7;
                *(uint4*)&sA[r][c8 * 8] =
                    *(const uint4*)(A + (size_t)r * H_ + kc + c8 * 8);
            }
            // B: 32 n-rows x 64 k fp16
#pragma unroll
            for (int it = 0; it < 2; it++) {
                int idx = tid + it * 128;
                int r = idx >> 3, c8 = idx & 7;
                *(uint4*)&sB[r][c8 * 8] =
                    *(const uint4*)(Bm + (size_t)(n0 + r) * H_ + kc + c8 * 8);
            }
            __syncthreads();
#pragma unroll
            for (int kk = 0; kk < 64; kk += 16) {
                uint32_t af[2][4], bf[2][2];
#pragma unroll
                for (int ms = 0; ms < 2; ms++) {
                    int rb = wm * 32 + ms * 16;
                    af[ms][0] = *(const uint32_t*)&sA[rb + g][kk + tg * 2];
                    af[ms][1] = *(const uint32_t*)&sA[rb + g + 8][kk + tg * 2];
                    af[ms][2] = *(const uint32_t*)&sA[rb + g][kk + tg * 2 + 8];
                    af[ms][3] = *(const uint32_t*)&sA[rb + g + 8][kk + tg * 2 + 8];
                }
#pragma unroll
                for (int ns = 0; ns < 2; ns++) {
                    int nc = wn * 16 + ns * 8 + g;
                    bf[ns][0] = *(const uint32_t*)&sB[nc][kk + tg * 2];
                    bf[ns][1] = *(const uint32_t*)&sB[nc][kk + tg * 2 + 8];
                }
#pragma unroll
                for (int ms = 0; ms < 2; ms++)
#pragma unroll
                    for (int ns = 0; ns < 2; ns++) mma16816(acc[ms][ns], af[ms], bf[ns]);
            }
        }
    }

    // epilogue
#pragma unroll
    for (int ms = 0; ms < 2; ms++)
#pragma unroll
        for (int ns = 0; ns < 2; ns++) {
            int n = n0 + wn * 16 + ns * 8 + tg * 2;
#pragma unroll
            for (int hh = 0; hh < 2; hh++) {
                int b = wm * 32 + ms * 16 + g + hh * 8;
                float v0 = acc[ms][ns][hh * 2 + 0];
                float v1 = acc[ms][ns][hh * 2 + 1];
                if (layer == 0) {
                    size_t xoff = ((size_t)(t + 1) * B_ + b) * H_ + n;
                    float h0a = tanhf(v0 + __half2float(g_X0[xoff])     + g_bias0[n]);
                    float h0b = tanhf(v1 + __half2float(g_X0[xoff + 1]) + g_bias0[n + 1]);
                    *(__half2*)&g_h0[1 - p][b * H_ + n] = __floats2half2_rn(h0a, h0b);
                    g_h0f[b * H_ + n]     = h0a;
                    g_h0f[b * H_ + n + 1] = h0b;
                } else {
                    float ha = tanhf(v0 + g_bias1[n]);
                    float hb = tanhf(v1 + g_bias1[n + 1]);
                    *(__half2*)&g_h1[1 - p][b * H_ + n] = __floats2half2_rn(ha, hb);
                    size_t ooff = ((size_t)b * S_ + t) * H_ + n;
                    out[ooff]     = ha;
                    out[ooff + 1] = hb;
                }
            }
        }
}

// ---------------- final: assemble hidden [2][B][H] after outputs --------------
__global__ void k_final(float* __restrict__ out) {
    int i = blockIdx.x * blockDim.x + threadIdx.x;
    if (i < B_ * H_) {
        int b = i >> 10, n = i & 1023;
        size_t base = (size_t)B_ * S_ * H_;
        out[base + i] = g_h0f[i];                                   // hidden[0]
        out[base + (size_t)B_ * H_ + i] =
            out[((size_t)b * S_ + (S_ - 1)) * H_ + n];              // hidden[1] = h1_{S-1}
    }
}

// ---------------- launch --------------------------------------------------
extern "C" void kernel_launch(void* const* d_in, const int* in_sizes, int n_in,
                              void* d_out, int out_size) {
    (void)in_sizes; (void)n_in; (void)out_size;
    const void*  src  = d_in[0];                  // int64 or int32 [B,S]
    const float* emb  = (const float*)d_in[1];    // [V,E]
    const float* Wih0 = (const float*)d_in[2];    // [E,H]
    const float* Whh0 = (const float*)d_in[3];    // [H,H]
    const float* bih0 = (const float*)d_in[4];
    const float* bhh0 = (const float*)d_in[5];
    const float* Wih1 = (const float*)d_in[6];    // [H,H]
    const float* Whh1 = (const float*)d_in[7];    // [H,H]
    const float* bih1 = (const float*)d_in[8];
    const float* bhh1 = (const float*)d_in[9];
    float* out = (float*)d_out;

    k_detect<<<1, 64>>>((const int*)src);
    k_convT<<<1024, 256>>>(Wih0, 0);
    k_convT<<<1024, 256>>>(Whh0, 1);
    k_convT<<<1024, 256>>>(Wih1, 2);
    k_convT<<<1024, 256>>>(Whh1, 3);
    k_bias<<<4, 256>>>(bih0, bhh0, bih1, bhh1);

    dim3 g1(16, 512);
    k_phase1<<<g1, 256>>>(src, emb);
    k_init<<<(B_ * H_ + 255) / 256, 256>>>();

    for (int t = 0; t < S_; t++) k_step<<<64, 128>>>(t, out);

    k_final<<<(B_ * H_ + 255) / 256, 256>>>(out);
}

// round 3
// speedup vs baseline: 1.0037x; 1.0037x over previous
#include <cuda_runtime.h>
#include <cuda_fp16.h>
#include <cstdint>
#include <cstddef>

// Problem shape (fixed by setup_inputs)
#define B_ 64
#define S_ 512
#define E_ 512
#define H_ 1024

// ---------------- device scratch (static; no cudaMalloc allowed) -------------
__device__ __half g_Wih0T[(size_t)H_ * E_];   // [n][e]  (transposed, fp16)
__device__ __half g_Whh0T[(size_t)H_ * H_];   // [n][k]
__device__ __half g_Wih1T[(size_t)H_ * H_];   // [n][k]
__device__ __half g_Whh1T[(size_t)H_ * H_];   // [n][k]
__device__ float  g_bias0[H_];
__device__ float  g_bias1[H_];
__device__ __half g_X0[(size_t)S_ * B_ * H_]; // [t][b][n] = (emb[src] @ W_ih0), fp16
__device__ __half g_h0[2][B_ * H_];           // ping-pong fp16 hidden, layer 0
__device__ __half g_h1[2][B_ * H_];           // ping-pong fp16 hidden, layer 1
__device__ float  g_h0f[B_ * H_];             // latest h0 in fp32 (for final hidden)
__device__ int    g_is64;                     // src dtype flag

// ---------------- mma.sync helper (m16n8k16 fp16 -> fp32) --------------------
__device__ __forceinline__ void mma16816(float* c, const uint32_t* a, const uint32_t* b) {
    asm volatile(
        "mma.sync.aligned.m16n8k16.row.col.f32.f16.f16.f32 "
        "{%0,%1,%2,%3}, {%4,%5,%6,%7}, {%8,%9}, {%0,%1,%2,%3};\n"
        : "+f"(c[0]), "+f"(c[1]), "+f"(c[2]), "+f"(c[3])
        : "r"(a[0]), "r"(a[1]), "r"(a[2]), "r"(a[3]), "r"(b[0]), "r"(b[1]));
}

// ---------------- src dtype detection (int64 vs int32) -----------------------
__global__ void k_detect(const int* src32) {
    __shared__ int bad;
    if (threadIdx.x == 0) bad = 0;
    __syncthreads();
    // If src is int64 (LE), odd 32-bit words are all-zero high words.
    if (src32[2 * threadIdx.x + 1] != 0) atomicExch(&bad, 1);
    __syncthreads();
    if (threadIdx.x == 0) g_is64 = bad ? 0 : 1;
}

// ---------------- weight transpose + fp16 convert ----------------------------
// dst[n*K + k] = w[k*H_ + n]   (all weight matrices have N = H_ output cols)
__global__ void k_convT(const float* __restrict__ w, int which) {
    __half* dst; int K;
    switch (which) {
        case 0:  dst = g_Wih0T; K = E_; break;
        case 1:  dst = g_Whh0T; K = H_; break;
        case 2:  dst = g_Wih1T; K = H_; break;
        default: dst = g_Whh1T; K = H_; break;
    }
    size_t total = (size_t)K * H_;
    for (size_t i = (size_t)blockIdx.x * blockDim.x + threadIdx.x; i < total;
         i += (size_t)gridDim.x * blockDim.x) {
        size_t n = i / (size_t)K;
        size_t k = i - n * (size_t)K;
        dst[i] = __float2half(w[k * H_ + n]);
    }
}

__global__ void k_bias(const float* bih0, const float* bhh0,
                       const float* bih1, const float* bhh1) {
    int i = blockIdx.x * blockDim.x + threadIdx.x;
    if (i < H_) {
        g_bias0[i] = bih0[i] + bhh0[i];
        g_bias1[i] = bih1[i] + bhh1[i];
    }
}

// ---------------- phase 1: X0 = emb[src] @ W_ih0 (gather-GEMM) ----------------
// CTA tile 64(M) x 64(N), K = 512, 256 threads = 8 warps (2M x 4N), warp 32x16.
// m = t*64 + b; a 64-aligned M-tile shares a single t = blockIdx.y.
__global__ void __launch_bounds__(256) k_phase1(const void* srcv, const float* __restrict__ emb) {
    __shared__ __half sA[64][72];
    __shared__ __half sB[64][72];
    __shared__ int    sSrc[64];

    const int* s32 = (const int*)srcv;
    int tid = threadIdx.x;
    int nt = blockIdx.x;          // 0..15
    int mt = blockIdx.y;          // 0..511 == t
    int n0 = nt * 64;

    if (tid < 64) {
        int idx = tid * S_ + mt;  // src[b][t], b = tid
        sSrc[tid] = g_is64 ? s32[2 * idx] : s32[idx];
    }
    __syncthreads();

    int warp = tid >> 5, lane = tid & 31;
    int g = lane >> 2, tg = lane & 3;
    int wm = warp >> 2, wn = warp & 3;

    float acc[2][2][4];
#pragma unroll
    for (int i = 0; i < 2; i++)
#pragma unroll
        for (int j = 0; j < 2; j++)
#pragma unroll
            for (int q = 0; q < 4; q++) acc[i][j][q] = 0.f;

    for (int kc = 0; kc < E_; kc += 64) {
        __syncthreads();
        // A: gather 64 embedding rows x 64 fp32, convert to fp16
#pragma unroll
        for (int it = 0; it < 4; it++) {
            int idx = tid + it * 256;
            int r = idx >> 4, c4 = idx & 15;
            float4 v = *(const float4*)(emb + (size_t)sSrc[r] * E_ + kc + c4 * 4);
            *(__half2*)&sA[r][c4 * 4]     = __floats2half2_rn(v.x, v.y);
            *(__half2*)&sA[r][c4 * 4 + 2] = __floats2half2_rn(v.z, v.w);
        }
        // B: 64 n-rows x 64 k fp16 from transposed weight
#pragma unroll
        for (int it = 0; it < 2; it++) {
            int idx = tid + it * 256;
            int r = idx >> 3, c8 = idx & 7;
            *(uint4*)&sB[r][c8 * 8] =
                *(const uint4*)(g_Wih0T + (size_t)(n0 + r) * E_ + kc + c8 * 8);
        }
        __syncthreads();
#pragma unroll
        for (int kk = 0; kk < 64; kk += 16) {
            uint32_t af[2][4], bf[2][2];
#pragma unroll
            for (int ms = 0; ms < 2; ms++) {
                int rb = wm * 32 + ms * 16;
                af[ms][0] = *(const uint32_t*)&sA[rb + g][kk + tg * 2];
                af[ms][1] = *(const uint32_t*)&sA[rb + g + 8][kk + tg * 2];
                af[ms][2] = *(const uint32_t*)&sA[rb + g][kk + tg * 2 + 8];
                af[ms][3] = *(const uint32_t*)&sA[rb + g + 8][kk + tg * 2 + 8];
            }
#pragma unroll
            for (int ns = 0; ns < 2; ns++) {
                int nc = wn * 16 + ns * 8 + g;
                bf[ns][0] = *(const uint32_t*)&sB[nc][kk + tg * 2];
                bf[ns][1] = *(const uint32_t*)&sB[nc][kk + tg * 2 + 8];
            }
#pragma unroll
            for (int ms = 0; ms < 2; ms++)
#pragma unroll
                for (int ns = 0; ns < 2; ns++) mma16816(acc[ms][ns], af[ms], bf[ns]);
        }
    }
    // epilogue: store X0 (fp16)
#pragma unroll
    for (int ms = 0; ms < 2; ms++)
#pragma unroll
        for (int ns = 0; ns < 2; ns++) {
            int n = n0 + wn * 16 + ns * 8 + tg * 2;
#pragma unroll
            for (int hh = 0; hh < 2; hh++) {
                int row = wm * 32 + ms * 16 + g + hh * 8;
                size_t m = (size_t)mt * 64 + row;
                *(__half2*)&g_X0[m * H_ + n] =
                    __floats2half2_rn(acc[ms][ns][hh * 2], acc[ms][ns][hh * 2 + 1]);
            }
        }
}

// ---------------- init: h0_0 = tanh(X0[0] + bias0), h1_{-1} = 0 ---------------
__global__ void k_init() {
    int i = blockIdx.x * blockDim.x + threadIdx.x;
    if (i < B_ * H_) {
        int n = i & (H_ - 1);
        float h = tanhf(__half2float(g_X0[i]) + g_bias0[n]);
        g_h0[0][i] = __float2half(h);
        g_h0f[i] = h;
        g_h1[0][i] = __float2half(0.f);
    }
}

// ---------------- step kernel: one launch per timestep ------------------------
// blocks 0..31  : layer0 -> h0_{t+1} = tanh(X0[t+1] + h0_t @ W_hh0 + bias0)
// blocks 32..63 : layer1 -> h1_t     = tanh(h0_t @ W_ih1 + h1_{t-1} @ W_hh1 + bias1)
// CTA tile 64(M=batch) x 32(N), 128 threads = 4 warps (2M x 2N), warp 32x16.
__global__ void __launch_bounds__(128) k_step(int t, float* __restrict__ out) {
    __shared__ __half sA[64][72];
    __shared__ __half sB[32][72];

    int tid = threadIdx.x;
    int warp = tid >> 5, lane = tid & 31;
    int g = lane >> 2, tg = lane & 3;
    int wm = warp >> 1, wn = warp & 1;
    int layer = (int)(blockIdx.x >> 5);
    int nt = (int)(blockIdx.x & 31);
    int n0 = nt * 32;
    int p = t & 1;

    if (layer == 0 && t + 1 >= S_) return;  // uniform per block

    float acc[2][2][4];
#pragma unroll
    for (int i = 0; i < 2; i++)
#pragma unroll
        for (int j = 0; j < 2; j++)
#pragma unroll
            for (int q = 0; q < 4; q++) acc[i][j][q] = 0.f;

    int nPh = (layer == 0) ? 1 : 2;
    for (int ph = 0; ph < nPh; ph++) {
        const __half* A = (ph == 0) ? g_h0[p] : g_h1[p];
        const __half* Bm = (layer == 0) ? g_Whh0T : ((ph == 0) ? g_Wih1T : g_Whh1T);
        for (int kc = 0; kc < H_; kc += 64) {
            __syncthreads();
            // A: 64 x 64 fp16 (full batch of h)
#pragma unroll
            for (int it = 0; it < 4; it++) {
                int idx = tid + it * 128;
                int r = idx >> 3, c8 = idx & 7;
                *(uint4*)&sA[r][c8 * 8] =
                    *(const uint4*)(A + (size_t)r * H_ + kc + c8 * 8);
            }
            // B: 32 n-rows x 64 k fp16
#pragma unroll
            for (int it = 0; it < 2; it++) {
                int idx = tid + it * 128;
                int r = idx >> 3, c8 = idx & 7;
                *(uint4*)&sB[r][c8 * 8] =
                    *(const uint4*)(Bm + (size_t)(n0 + r) * H_ + kc + c8 * 8);
            }
            __syncthreads();
#pragma unroll
            for (int kk = 0; kk < 64; kk += 16) {
                uint32_t af[2][4], bf[2][2];
#pragma unroll
                for (int ms = 0; ms < 2; ms++) {
                    int rb = wm * 32 + ms * 16;
                    af[ms][0] = *(const uint32_t*)&sA[rb + g][kk + tg * 2];
                    af[ms][1] = *(const uint32_t*)&sA[rb + g + 8][kk + tg * 2];
                    af[ms][2] = *(const uint32_t*)&sA[rb + g][kk + tg * 2 + 8];
                    af[ms][3] = *(const uint32_t*)&sA[rb + g + 8][kk + tg * 2 + 8];
                }
#pragma unroll
                for (int ns = 0; ns < 2; ns++) {
                    int nc = wn * 16 + ns * 8 + g;
                    bf[ns][0] = *(const uint32_t*)&sB[nc][kk + tg * 2];
                    bf[ns][1] = *(const uint32_t*)&sB[nc][kk + tg * 2 + 8];
                }
#pragma unroll
                for (int ms = 0; ms < 2; ms++)
#pragma unroll
                    for (int ns = 0; ns < 2; ns++) mma16816(acc[ms][ns], af[ms], bf[ns]);
            }
        }
    }

    // epilogue
#pragma unroll
    for (int ms = 0; ms < 2; ms++)
#pragma unroll
        for (int ns = 0; ns < 2; ns++) {
            int n = n0 + wn * 16 + ns * 8 + tg * 2;
#pragma unroll
            for (int hh = 0; hh < 2; hh++) {
                int b = wm * 32 + ms * 16 + g + hh * 8;
                float v0 = acc[ms][ns][hh * 2 + 0];
                float v1 = acc[ms][ns][hh * 2 + 1];
                if (layer == 0) {
                    size_t xoff = ((size_t)(t + 1) * B_ + b) * H_ + n;
                    float h0a = tanhf(v0 + __half2float(g_X0[xoff])     + g_bias0[n]);
                    float h0b = tanhf(v1 + __half2float(g_X0[xoff + 1]) + g_bias0[n + 1]);
                    *(__half2*)&g_h0[1 - p][b * H_ + n] = __floats2half2_rn(h0a, h0b);
                    g_h0f[b * H_ + n]     = h0a;
                    g_h0f[b * H_ + n + 1] = h0b;
                } else {
                    float ha = tanhf(v0 + g_bias1[n]);
                    float hb = tanhf(v1 + g_bias1[n + 1]);
                    *(__half2*)&g_h1[1 - p][b * H_ + n] = __floats2half2_rn(ha, hb);
                    size_t ooff = ((size_t)b * S_ + t) * H_ + n;
                    out[ooff]     = ha;
                    out[ooff + 1] = hb;
                }
            }
        }
}

// ---------------- final: assemble hidden [2][B][H] after outputs --------------
__global__ void k_final(float* __restrict__ out) {
    int i = blockIdx.x * blockDim.x + threadIdx.x;
    if (i < B_ * H_) {
        int b = i >> 10, n = i & 1023;
        size_t base = (size_t)B_ * S_ * H_;
        out[base + i] = g_h0f[i];                                   // hidden[0]
        out[base + (size_t)B_ * H_ + i] =
            out[((size_t)b * S_ + (S_ - 1)) * H_ + n];              // hidden[1] = h1_{S-1}
    }
}

// ---------------- launch --------------------------------------------------
extern "C" void kernel_launch(void* const* d_in, const int* in_sizes, int n_in,
                              void* d_out, int out_size) {
    (void)in_sizes; (void)n_in; (void)out_size;
    const void*  src  = d_in[0];                  // int64 or int32 [B,S]
    const float* emb  = (const float*)d_in[1];    // [V,E]
    const float* Wih0 = (const float*)d_in[2];    // [E,H]
    const float* Whh0 = (const float*)d_in[3];    // [H,H]
    const float* bih0 = (const float*)d_in[4];
    const float* bhh0 = (const float*)d_in[5];
    const float* Wih1 = (const float*)d_in[6];    // [H,H]
    const float* Whh1 = (const float*)d_in[7];    // [H,H]
    const float* bih1 = (const float*)d_in[8];
    const float* bhh1 = (const float*)d_in[9];
    float* out = (float*)d_out;

    k_detect<<<1, 64>>>((const int*)src);
    k_convT<<<1024, 256>>>(Wih0, 0);
    k_convT<<<1024, 256>>>(Whh0, 1);
    k_convT<<<1024, 256>>>(Wih1, 2);
    k_convT<<<1024, 256>>>(Whh1, 3);
    k_bias<<<4, 256>>>(bih0, bhh0, bih1, bhh1);

    dim3 g1(16, 512);
    k_phase1<<<g1, 256>>>(src, emb);
    k_init<<<(B_ * H_ + 255) / 256, 256>>>();

    for (int t = 0; t < S_; t++) k_step<<<64, 128>>>(t, out);

    k_final<<<(B_ * H_ + 255) / 256, 256>>>(out);
}

// round 4
// speedup vs baseline: 1.6575x; 1.6514x over previous
#include <cuda_runtime.h>
#include <cuda_fp16.h>
#include <cstdint>
#include <cstddef>

#define B_ 64
#define S_ 512
#define E_ 512
#define H_ 1024
#define NCTA 48

// ---------------- device scratch ---------------------------------------------
__device__ __half g_Wih0T[(size_t)H_ * E_];   // [n][e]
__device__ __half g_Whh0T[(size_t)H_ * H_];   // [n][k]
__device__ __half g_Wih1T[(size_t)H_ * H_];
__device__ __half g_Whh1T[(size_t)H_ * H_];
__device__ float  g_bias0[H_];
__device__ float  g_bias1[H_];
__device__ __half g_X0[(size_t)S_ * B_ * H_]; // [t][b][n]
__device__ __half g_h0[2][B_ * H_];
__device__ __half g_h1[2][B_ * H_];
__device__ float  g_h0f[B_ * H_];
__device__ int    g_is64;

__device__ float            g_partial[NCTA][B_ * 128];
__device__ volatile unsigned g_flag[NCTA];
__device__ unsigned          g_bar_count;
__device__ volatile unsigned g_bar_gen;

// ---------------- helpers ----------------------------------------------------
__device__ __forceinline__ void mma16816(float* c, const uint32_t* a, const uint32_t* b) {
    asm volatile(
        "mma.sync.aligned.m16n8k16.row.col.f32.f16.f16.f32 "
        "{%0,%1,%2,%3}, {%4,%5,%6,%7}, {%8,%9}, {%0,%1,%2,%3};\n"
        : "+f"(c[0]), "+f"(c[1]), "+f"(c[2]), "+f"(c[3])
        : "r"(a[0]), "r"(a[1]), "r"(a[2]), "r"(a[3]), "r"(b[0]), "r"(b[1]));
}
__device__ __forceinline__ void cp_async16(void* sptr, const void* gptr) {
    unsigned s = (unsigned)__cvta_generic_to_shared(sptr);
    asm volatile("cp.async.cg.shared.global [%0], [%1], 16;\n" :: "r"(s), "l"(gptr));
}
__device__ __forceinline__ void cp_commit() { asm volatile("cp.async.commit_group;\n"); }
template <int N>
__device__ __forceinline__ void cp_wait() { asm volatile("cp.async.wait_group %0;\n" :: "n"(N)); }

// ---------------- src dtype detection ----------------------------------------
__global__ void k_detect(const int* src32) {
    __shared__ int bad;
    if (threadIdx.x == 0) bad = 0;
    __syncthreads();
    if (src32[2 * threadIdx.x + 1] != 0) atomicExch(&bad, 1);
    __syncthreads();
    if (threadIdx.x == 0) g_is64 = bad ? 0 : 1;
}

// ---------------- weight transpose + fp16 convert ----------------------------
__global__ void k_convT(const float* __restrict__ w, int which) {
    __half* dst; int K;
    switch (which) {
        case 0:  dst = g_Wih0T; K = E_; break;
        case 1:  dst = g_Whh0T; K = H_; break;
        case 2:  dst = g_Wih1T; K = H_; break;
        default: dst = g_Whh1T; K = H_; break;
    }
    size_t total = (size_t)K * H_;
    for (size_t i = (size_t)blockIdx.x * blockDim.x + threadIdx.x; i < total;
         i += (size_t)gridDim.x * blockDim.x) {
        size_t n = i / (size_t)K;
        size_t k = i - n * (size_t)K;
        dst[i] = __float2half(w[k * H_ + n]);
    }
}

__global__ void k_bias(const float* bih0, const float* bhh0,
                       const float* bih1, const float* bhh1) {
    int i = blockIdx.x * blockDim.x + threadIdx.x;
    if (i < H_) {
        g_bias0[i] = bih0[i] + bhh0[i];
        g_bias1[i] = bih1[i] + bhh1[i];
    }
}

// ---------------- phase 1: X0 = emb[src] @ W_ih0 -----------------------------
__global__ void __launch_bounds__(256) k_phase1(const void* srcv, const float* __restrict__ emb) {
    __shared__ __half sA[64][72];
    __shared__ __half sB[64][72];
    __shared__ int    sSrc[64];

    const int* s32 = (const int*)srcv;
    int tid = threadIdx.x;
    int nt = blockIdx.x;
    int mt = blockIdx.y;
    int n0 = nt * 64;

    if (tid < 64) {
        int idx = tid * S_ + mt;
        sSrc[tid] = g_is64 ? s32[2 * idx] : s32[idx];
    }
    __syncthreads();

    int warp = tid >> 5, lane = tid & 31;
    int g = lane >> 2, tg = lane & 3;
    int wm = warp >> 2, wn = warp & 3;

    float acc[2][2][4];
#pragma unroll
    for (int i = 0; i < 2; i++)
#pragma unroll
        for (int j = 0; j < 2; j++)
#pragma unroll
            for (int q = 0; q < 4; q++) acc[i][j][q] = 0.f;

    for (int kc = 0; kc < E_; kc += 64) {
        __syncthreads();
#pragma unroll
        for (int it = 0; it < 4; it++) {
            int idx = tid + it * 256;
            int r = idx >> 4, c4 = idx & 15;
            float4 v = *(const float4*)(emb + (size_t)sSrc[r] * E_ + kc + c4 * 4);
            *(__half2*)&sA[r][c4 * 4]     = __floats2half2_rn(v.x, v.y);
            *(__half2*)&sA[r][c4 * 4 + 2] = __floats2half2_rn(v.z, v.w);
        }
#pragma unroll
        for (int it = 0; it < 2; it++) {
            int idx = tid + it * 256;
            int r = idx >> 3, c8 = idx & 7;
            *(uint4*)&sB[r][c8 * 8] =
                *(const uint4*)(g_Wih0T + (size_t)(n0 + r) * E_ + kc + c8 * 8);
        }
        __syncthreads();
#pragma unroll
        for (int kk = 0; kk < 64; kk += 16) {
            uint32_t af[2][4], bf[2][2];
#pragma unroll
            for (int ms = 0; ms < 2; ms++) {
                int rb = wm * 32 + ms * 16;
                af[ms][0] = *(const uint32_t*)&sA[rb + g][kk + tg * 2];
                af[ms][1] = *(const uint32_t*)&sA[rb + g + 8][kk + tg * 2];
                af[ms][2] = *(const uint32_t*)&sA[rb + g][kk + tg * 2 + 8];
                af[ms][3] = *(const uint32_t*)&sA[rb + g + 8][kk + tg * 2 + 8];
            }
#pragma unroll
            for (int ns = 0; ns < 2; ns++) {
                int nc = wn * 16 + ns * 8 + g;
                bf[ns][0] = *(const uint32_t*)&sB[nc][kk + tg * 2];
                bf[ns][1] = *(const uint32_t*)&sB[nc][kk + tg * 2 + 8];
            }
#pragma unroll
            for (int ms = 0; ms < 2; ms++)
#pragma unroll
                for (int ns = 0; ns < 2; ns++) mma16816(acc[ms][ns], af[ms], bf[ns]);
        }
    }
#pragma unroll
    for (int ms = 0; ms < 2; ms++)
#pragma unroll
        for (int ns = 0; ns < 2; ns++) {
            int n = n0 + wn * 16 + ns * 8 + tg * 2;
#pragma unroll
            for (int hh = 0; hh < 2; hh++) {
                int row = wm * 32 + ms * 16 + g + hh * 8;
                size_t m = (size_t)mt * 64 + row;
                *(__half2*)&g_X0[m * H_ + n] =
                    __floats2half2_rn(acc[ms][ns][hh * 2], acc[ms][ns][hh * 2 + 1]);
            }
        }
}

// ---------------- init (also resets flags each launch) ------------------------
__global__ void k_init() {
    int i = blockIdx.x * blockDim.x + threadIdx.x;
    if (i < NCTA) g_flag[i] = 0u;
    if (i < B_ * H_) {
        int n = i & (H_ - 1);
        float h = tanhf(__half2float(g_X0[i]) + g_bias0[n]);
        g_h0[0][i] = __float2half(h);
        g_h0f[i] = h;
        g_h1[0][i] = __float2half(0.f);
    }
}

// ---------------- persistent recurrent kernel --------------------------------
// CTA 0..15  (grp0): h0_t @ Whh0  [nt = idx>>1, K-half kh = idx&1]; kh==0 finishes h0_{t+1}
// CTA 16..31 (grp1): h0_t @ Wih1  partials only
// CTA 32..47 (grp2): h1_{t-1} @ Whh1; kh==0 finishes h1_t (adds own + 3 partials)
#define SA_STRIDE 72
#define SA_BUF (64 * SA_STRIDE)
#define BFRAG_BYTES (32 * 16 * 32 * 8)
#define DYN_SMEM (BFRAG_BYTES + 2 * SA_BUF * 2)

__device__ __forceinline__ void grid_barrier() {
    __syncthreads();
    if (threadIdx.x == 0) {
        unsigned gen = g_bar_gen;
        __threadfence();
        if (atomicAdd(&g_bar_count, 1u) == NCTA - 1) {
            g_bar_count = 0u;
            __threadfence();
            g_bar_gen = gen + 1u;
        } else {
            while (g_bar_gen == gen) { }
        }
        __threadfence();
    }
    __syncthreads();
}

__global__ void __launch_bounds__(128) k_persist(float* __restrict__ out) {
    extern __shared__ __align__(16) unsigned char dyn[];
    uint2*  bFrag = (uint2*)dyn;                    // [ksl 0..31][nblk 0..15][lane]
    __half* sAh   = (__half*)(dyn + BFRAG_BYTES);   // [2][64][72]

    const int tid  = threadIdx.x;
    const int warp = tid >> 5, lane = tid & 31;
    const int g = lane >> 2, tg = lane & 3;
    const int cta = blockIdx.x;
    const int grp = cta >> 4;          // 0: Whh0, 1: Wih1, 2: Whh1
    const int idx = cta & 15;
    const int nt  = idx >> 1;
    const int kh  = idx & 1;
    const int n0  = nt * 128;
    const bool finisher = (kh == 0) && (grp != 1);

    const __half* WT = (grp == 0) ? g_Whh0T : (grp == 1) ? g_Wih1T : g_Whh1T;

    // ---- pack resident weight fragments (once) ----
    for (int i = tid; i < 32 * 16 * 32; i += 128) {
        int li  = i & 31;
        int nb  = (i >> 5) & 15;
        int ksl = i >> 9;
        int gi = li >> 2, tgi = li & 3;
        size_t n  = (size_t)(n0 + nb * 8 + gi);
        size_t kb = (size_t)kh * 512 + (size_t)ksl * 16 + tgi * 2;
        uint2 v;
        v.x = *(const uint32_t*)(WT + n * H_ + kb);
        v.y = *(const uint32_t*)(WT + n * H_ + kb + 8);
        bFrag[i] = v;
    }
    __syncthreads();

    for (int t = 0; t < S_; t++) {
        const int p = t & 1;
        const bool active = !(grp == 0 && t == S_ - 1);
        const unsigned stamp = (unsigned)t + 1u;

        if (active) {
            const __half* Abase = (grp == 2) ? g_h1[p] : g_h0[p];
            const __half* Asrc  = Abase + kh * 512;

            float acc[4][4][4];
#pragma unroll
            for (int a = 0; a < 4; a++)
#pragma unroll
                for (int b = 0; b < 4; b++)
#pragma unroll
                    for (int q = 0; q < 4; q++) acc[a][b][q] = 0.f;

            // prologue: chunk 0 (64 rows x 64 k)
#pragma unroll
            for (int it = 0; it < 4; it++) {
                int ii = tid + it * 128;
                int r = ii >> 3, s8 = ii & 7;
                cp_async16(sAh + r * SA_STRIDE + s8 * 8, Asrc + (size_t)r * H_ + s8 * 8);
            }
            cp_commit();

            for (int c = 0; c < 8; c++) {
                if (c < 7) {
                    int buf = (c + 1) & 1;
#pragma unroll
                    for (int it = 0; it < 4; it++) {
                        int ii = tid + it * 128;
                        int r = ii >> 3, s8 = ii & 7;
                        cp_async16(sAh + buf * SA_BUF + r * SA_STRIDE + s8 * 8,
                                   Asrc + (size_t)r * H_ + (c + 1) * 64 + s8 * 8);
                    }
                    cp_commit();
                    cp_wait<1>();
                } else {
                    cp_wait<0>();
                }
                __syncthreads();

                const __half* sAb = sAh + (c & 1) * SA_BUF;
#pragma unroll
                for (int kk = 0; kk < 4; kk++) {
                    uint32_t af[4][4];
#pragma unroll
                    for (int ms = 0; ms < 4; ms++) {
                        const __half* base = sAb + (ms * 16 + g) * SA_STRIDE + kk * 16 + tg * 2;
                        af[ms][0] = *(const uint32_t*)base;
                        af[ms][1] = *(const uint32_t*)(base + 8 * SA_STRIDE);
                        af[ms][2] = *(const uint32_t*)(base + 8);
                        af[ms][3] = *(const uint32_t*)(base + 8 * SA_STRIDE + 8);
                    }
                    int kslg = c * 4 + kk;
                    uint2 bf[4];
#pragma unroll
                    for (int ns = 0; ns < 4; ns++)
                        bf[ns] = bFrag[(kslg * 16 + warp * 4 + ns) * 32 + lane];
#pragma unroll
                    for (int ms = 0; ms < 4; ms++)
#pragma unroll
                        for (int ns = 0; ns < 4; ns++)
                            mma16816(acc[ms][ns], af[ms], (const uint32_t*)&bf[ns]);
                }
                __syncthreads();
            }

            if (!finisher) {
#pragma unroll
                for (int ms = 0; ms < 4; ms++)
#pragma unroll
                    for (int ns = 0; ns < 4; ns++)
#pragma unroll
                        for (int hh = 0; hh < 2; hh++) {
                            int row = ms * 16 + g + hh * 8;
                            int nl = warp * 32 + ns * 8 + tg * 2;
                            float2 v = make_float2(acc[ms][ns][hh * 2], acc[ms][ns][hh * 2 + 1]);
                            __stcg((float2*)&g_partial[cta][row * 128 + nl], v);
                        }
                __syncthreads();
                if (tid == 0) {
                    __threadfence();
                    g_flag[cta] = stamp;
                }
            } else {
                if (tid == 0) {
                    while (g_flag[cta + 1] < stamp) { }
                    if (grp == 2) {
                        while (g_flag[16 + idx] < stamp) { }
                        while (g_flag[16 + idx + 1] < stamp) { }
                    }
                    __threadfence();
                }
                __syncthreads();

#pragma unroll
                for (int ms = 0; ms < 4; ms++)
#pragma unroll
                    for (int ns = 0; ns < 4; ns++)
#pragma unroll
                        for (int hh = 0; hh < 2; hh++) {
                            int row = ms * 16 + g + hh * 8;
                            int nl = warp * 32 + ns * 8 + tg * 2;
                            int n = n0 + nl;
                            float sx = acc[ms][ns][hh * 2], sy = acc[ms][ns][hh * 2 + 1];
                            float2 q1 = __ldcg((const float2*)&g_partial[cta + 1][row * 128 + nl]);
                            sx += q1.x; sy += q1.y;
                            if (grp == 0) {
                                size_t xoff = ((size_t)(t + 1) * B_ + row) * H_ + n;
                                float h0a = tanhf(sx + __half2float(g_X0[xoff])     + g_bias0[n]);
                                float h0b = tanhf(sy + __half2float(g_X0[xoff + 1]) + g_bias0[n + 1]);
                                __half2 hv = __floats2half2_rn(h0a, h0b);
                                __stcg((unsigned*)&g_h0[1 - p][row * H_ + n], *(unsigned*)&hv);
                                if (t == S_ - 2) {
                                    g_h0f[row * H_ + n]     = h0a;
                                    g_h0f[row * H_ + n + 1] = h0b;
                                }
                            } else {
                                float2 q2 = __ldcg((const float2*)&g_partial[16 + idx][row * 128 + nl]);
                                float2 q3 = __ldcg((const float2*)&g_partial[16 + idx + 1][row * 128 + nl]);
                                sx += q2.x + q3.x;
                                sy += q2.y + q3.y;
                                float ha = tanhf(sx + g_bias1[n]);
                                float hb = tanhf(sy + g_bias1[n + 1]);
                                __half2 hv = __floats2half2_rn(ha, hb);
                                __stcg((unsigned*)&g_h1[1 - p][row * H_ + n], *(unsigned*)&hv);
                                size_t ooff = ((size_t)row * S_ + t) * H_ + n;
                                out[ooff]     = ha;
                                out[ooff + 1] = hb;
                            }
                        }
            }
        }
        grid_barrier();
    }
}

// ---------------- final hidden assembly --------------------------------------
__global__ void k_final(float* __restrict__ out) {
    int i = blockIdx.x * blockDim.x + threadIdx.x;
    if (i < B_ * H_) {
        int b = i >> 10, n = i & 1023;
        size_t base = (size_t)B_ * S_ * H_;
        out[base + i] = g_h0f[i];
        out[base + (size_t)B_ * H_ + i] =
            out[((size_t)b * S_ + (S_ - 1)) * H_ + n];
    }
}

// ---------------- launch ------------------------------------------------------
extern "C" void kernel_launch(void* const* d_in, const int* in_sizes, int n_in,
                              void* d_out, int out_size) {
    (void)in_sizes; (void)n_in; (void)out_size;
    const void*  src  = d_in[0];
    const float* emb  = (const float*)d_in[1];
    const float* Wih0 = (const float*)d_in[2];
    const float* Whh0 = (const float*)d_in[3];
    const float* bih0 = (const float*)d_in[4];
    const float* bhh0 = (const float*)d_in[5];
    const float* Wih1 = (const float*)d_in[6];
    const float* Whh1 = (const float*)d_in[7];
    const float* bih1 = (const float*)d_in[8];
    const float* bhh1 = (const float*)d_in[9];
    float* out = (float*)d_out;

    cudaFuncSetAttribute(k_persist, cudaFuncAttributeMaxDynamicSharedMemorySize, DYN_SMEM);

    k_detect<<<1, 64>>>((const int*)src);
    k_convT<<<1024, 256>>>(Wih0, 0);
    k_convT<<<1024, 256>>>(Whh0, 1);
    k_convT<<<1024, 256>>>(Wih1, 2);
    k_convT<<<1024, 256>>>(Whh1, 3);
    k_bias<<<4, 256>>>(bih0, bhh0, bih1, bhh1);

    dim3 g1(16, 512);
    k_phase1<<<g1, 256>>>(src, emb);
    k_init<<<(B_ * H_ + 255) / 256, 256>>>();

    k_persist<<<NCTA, 128, DYN_SMEM>>>(out);

    k_final<<<(B_ * H_ + 255) / 256, 256>>>(out);
}